// round 17
// baseline (speedup 1.0000x reference)
#include <cuda_runtime.h>
#include <cuda_fp16.h>
#include <stdint.h>

#define D_IN   256
#define D_HID  64
#define D_EMB  32
#define MAX_NODES 100000

// Scratch (static __device__ — no allocation allowed)
__device__ __half g_Hh [MAX_NODES * D_HID];  // x @ W1            (fp16)
__device__ float  g_S1 [MAX_NODES * D_HID];  // A @ H             (fp32)
__device__ __half g_Z1h[MAX_NODES * D_EMB];  // relu(S1+b1) @ W2  (fp16)
__device__ float  g_S2 [MAX_NODES * D_EMB];  // A @ Z1            (fp32)
__device__ __half g_S2h[MAX_NODES * D_EMB];  // fp16 (S2+b2) for decoder

// ---------------------------------------------------------------------------
// TF32 helpers
// ---------------------------------------------------------------------------
__device__ __forceinline__ unsigned f2tf32(float f) {
    unsigned r;
    asm("cvt.rna.tf32.f32 %0, %1;" : "=r"(r) : "f"(f));
    return r;
}
__device__ __forceinline__ unsigned bits2tf32(unsigned b) {
    unsigned r;
    asm("cvt.rna.tf32.f32 %0, %1;" : "=r"(r) : "r"(b));
    return r;
}

__device__ __forceinline__ void mma_tf32(
    float& d0, float& d1, float& d2, float& d3,
    unsigned a0, unsigned a1, unsigned a2, unsigned a3,
    unsigned b0, unsigned b1)
{
    asm volatile(
        "mma.sync.aligned.m16n8k8.row.col.f32.tf32.tf32.f32 "
        "{%0,%1,%2,%3}, {%4,%5,%6,%7}, {%8,%9}, {%0,%1,%2,%3};"
        : "+f"(d0), "+f"(d1), "+f"(d2), "+f"(d3)
        : "r"(a0), "r"(a1), "r"(a2), "r"(a3), "r"(b0), "r"(b1));
}

__device__ __forceinline__ void cp_async16(unsigned smem_addr, const void* gptr) {
    asm volatile("cp.async.cg.shared.global [%0], [%1], 16;"
                 :: "r"(smem_addr), "l"(gptr));
}

// ---------------------------------------------------------------------------
// GEMM1 (TF32 + cp.async double buffer + fused zeroing), fp16 output.
// W1 staged in FRAGMENT ORDER: frag[(kc*4+k8)][chunk 0..3][lane][4 words]
// so each warp's B operands for one k8 are 4 conflict-free LDS.128.
//   word for W[k][col]:  k = kc*32 + k8*8 + h*4 + qcol  (h = 0 -> b0, 1 -> b1)
//                        col = nt*8 + qrow,  lane = qrow*4 + qcol
//        idx16 = nt*2 + h
//        addr  = (kc*4+k8)*512 + (idx16>>2)*128 + lane*4 + (idx16&3)
// SMEM: Wfrag 64KB + x fp32 [2][128][36] 36.9KB = 100.9KB -> 2 blocks/SM.
// ---------------------------------------------------------------------------
#define X_STRIDE 36
#define WF_WORDS (32 * 512)                   // 16384 words = 64 KB
#define X_WORDS  (128 * X_STRIDE)
#define GEMM1_SMEM ((WF_WORDS + 2 * X_WORDS) * 4)   // 102400 + 1... = 103,  (16384+9216)*4 = 102400 B

__global__ __launch_bounds__(256) void gemm1_tf32_v7(
    const float* __restrict__ x, const float* __restrict__ W1, int n)
{
    extern __shared__ unsigned smem[];
    unsigned* Wf  = smem;                       // fragment-order W1
    float*    xsf = (float*)(smem + WF_WORDS);  // [2][128][36]

    int tid  = threadIdx.x;
    int warp = tid >> 5;
    int lane = tid & 31;
    int row_base = blockIdx.x * 128;
    int wm   = warp * 16;
    int qrow = lane >> 2;
    int qcol = lane & 3;

    unsigned xs_base;
    asm("{ .reg .u64 t; cvta.to.shared.u64 t, %1; cvt.u32.u64 %0, t; }"
        : "=r"(xs_base) : "l"(xsf));

    // prefetch x chunk 0 into buffer 0
    #pragma unroll
    for (int l = 0; l < 4; l++) {
        int flat = tid + l * 256;
        int r    = flat >> 3;
        int c4   = flat & 7;
        int grow = row_base + r; if (grow >= n) grow = n - 1;
        cp_async16(xs_base + (unsigned)(r * X_STRIDE + c4 * 4) * 4,
                   x + (size_t)grow * D_IN + c4 * 4);
    }
    asm volatile("cp.async.commit_group;");

    // stage whole W1 (tf32) in fragment order
    #pragma unroll
    for (int l = 0; l < 16; l++) {
        int flat = tid + l * 256;       // float4 index over 256x64 (4096)
        int k  = flat >> 4;
        int cc = (flat & 15) * 4;       // col base (4 consecutive cols)
        float4 w = __ldg((const float4*)(W1 + (size_t)k * 64 + cc));
        int kc   = k >> 5;
        int k8   = (k >> 3) & 3;
        int h    = (k >> 2) & 1;
        int qc   = k & 3;
        unsigned wv[4] = { f2tf32(w.x), f2tf32(w.y), f2tf32(w.z), f2tf32(w.w) };
        #pragma unroll
        for (int j = 0; j < 4; j++) {
            int col = cc + j;
            int nt  = col >> 3;
            int qr  = col & 7;
            int ln  = qr * 4 + qc;
            int idx16 = nt * 2 + h;
            Wf[(kc * 4 + k8) * 512 + (idx16 >> 2) * 128 + ln * 4 + (idx16 & 3)] = wv[j];
        }
    }

    // fused zeroing of S1 / S2 (scatter targets)
    {
        int gtid = blockIdx.x * 256 + tid;
        int nthr = gridDim.x * 256;
        float4 z = make_float4(0.f, 0.f, 0.f, 0.f);
        for (int i = gtid; i < n * 16; i += nthr) ((float4*)g_S1)[i] = z;
        for (int i = gtid; i < n * 8;  i += nthr) ((float4*)g_S2)[i] = z;
    }

    float c[8][4];
    #pragma unroll
    for (int nt = 0; nt < 8; nt++)
        #pragma unroll
        for (int i = 0; i < 4; i++) c[nt][i] = 0.f;

    #pragma unroll
    for (int kc = 0; kc < 8; kc++) {
        if (kc + 1 < 8) {
            int buf = (kc + 1) & 1;
            #pragma unroll
            for (int l = 0; l < 4; l++) {
                int flat = tid + l * 256;
                int r    = flat >> 3;
                int c4   = flat & 7;
                int grow = row_base + r; if (grow >= n) grow = n - 1;
                cp_async16(xs_base + (unsigned)(buf * X_WORDS + r * X_STRIDE + c4 * 4) * 4,
                           x + (size_t)grow * D_IN + (kc + 1) * 32 + c4 * 4);
            }
            asm volatile("cp.async.commit_group;");
            asm volatile("cp.async.wait_group 1;");
        } else {
            asm volatile("cp.async.wait_group 0;");
        }
        __syncthreads();

        const unsigned* xb = (const unsigned*)(xsf + (kc & 1) * X_WORDS);
        #pragma unroll
        for (int k8 = 0; k8 < 4; k8++) {
            int ar = wm + qrow;
            int ac = k8 * 8 + qcol;
            unsigned a0 = bits2tf32(xb[(ar    ) * X_STRIDE + ac    ]);
            unsigned a1 = bits2tf32(xb[(ar + 8) * X_STRIDE + ac    ]);
            unsigned a2 = bits2tf32(xb[(ar    ) * X_STRIDE + ac + 4]);
            unsigned a3 = bits2tf32(xb[(ar + 8) * X_STRIDE + ac + 4]);

            // B fragments: 4 conflict-free LDS.128 (lane-consecutive)
            const uint4* fb = (const uint4*)&Wf[(kc * 4 + k8) * 512];
            uint4 u0 = fb[0 * 32 + lane];   // idx16  0..3  -> nt0.b0 nt0.b1 nt1.b0 nt1.b1
            uint4 u1 = fb[1 * 32 + lane];   // idx16  4..7
            uint4 u2 = fb[2 * 32 + lane];   // idx16  8..11
            uint4 u3 = fb[3 * 32 + lane];   // idx16 12..15

            mma_tf32(c[0][0], c[0][1], c[0][2], c[0][3], a0, a1, a2, a3, u0.x, u0.y);
            mma_tf32(c[1][0], c[1][1], c[1][2], c[1][3], a0, a1, a2, a3, u0.z, u0.w);
            mma_tf32(c[2][0], c[2][1], c[2][2], c[2][3], a0, a1, a2, a3, u1.x, u1.y);
            mma_tf32(c[3][0], c[3][1], c[3][2], c[3][3], a0, a1, a2, a3, u1.z, u1.w);
            mma_tf32(c[4][0], c[4][1], c[4][2], c[4][3], a0, a1, a2, a3, u2.x, u2.y);
            mma_tf32(c[5][0], c[5][1], c[5][2], c[5][3], a0, a1, a2, a3, u2.z, u2.w);
            mma_tf32(c[6][0], c[6][1], c[6][2], c[6][3], a0, a1, a2, a3, u3.x, u3.y);
            mma_tf32(c[7][0], c[7][1], c[7][2], c[7][3], a0, a1, a2, a3, u3.z, u3.w);
        }
        __syncthreads();
    }

    int r0 = row_base + wm + qrow;
    int cb = qcol * 2;
    #pragma unroll
    for (int nt = 0; nt < 8; nt++) {
        if (r0 < n)
            *(__half2*)(g_Hh + (size_t)r0 * D_HID + nt*8 + cb) =
                __floats2half2_rn(c[nt][0], c[nt][1]);
        if (r0 + 8 < n)
            *(__half2*)(g_Hh + (size_t)(r0 + 8) * D_HID + nt*8 + cb) =
                __floats2half2_rn(c[nt][2], c[nt][3]);
    }
}

// ---------------------------------------------------------------------------
// red helper
// ---------------------------------------------------------------------------
__device__ __forceinline__ void red_add_v4(float* p, float4 v) {
    asm volatile("red.global.add.v4.f32 [%0], {%1,%2,%3,%4};"
                 :: "l"(p), "f"(v.x), "f"(v.y), "f"(v.z), "f"(v.w)
                 : "memory");
}

// ---------------------------------------------------------------------------
// SpMM d=64: warp owns 32 edges; coalesced streaming index loads + shfl.
// ---------------------------------------------------------------------------
__global__ __launch_bounds__(256) void spmm64_kernel(
    const int* __restrict__ src, const int* __restrict__ dst,
    const float* __restrict__ val, int nnz)
{
    int lane = threadIdx.x & 31;
    long long wid = (long long)((blockIdx.x * blockDim.x + threadIdx.x) >> 5);
    long long wbase = wid * 32;
    if (wbase >= nnz) return;

    long long e = wbase + lane;
    bool ok = (e < nnz);
    long long ec = ok ? e : (nnz - 1);
    int   s = __ldcs(src + ec);
    int   d = __ldcs(dst + ec);
    float v = ok ? __ldcs(val + ec) : 0.f;

    int g = lane >> 4;          // group 0/1
    int c = lane & 15;          // channel quad

    #pragma unroll
    for (int j = 0; j < 16; j++) {
        int sl = g * 16 + j;
        int   sj = __shfl_sync(0xFFFFFFFFu, s, sl);
        int   dj = __shfl_sync(0xFFFFFFFFu, d, sl);
        float vj = __shfl_sync(0xFFFFFFFFu, v, sl);
        uint2 raw = __ldg((const uint2*)(g_Hh + (size_t)sj * D_HID) + c);
        float2 f0 = __half22float2(*(__half2*)&raw.x);
        float2 f1 = __half22float2(*(__half2*)&raw.y);
        red_add_v4(g_S1 + (size_t)dj * D_HID + c * 4,
                   make_float4(vj*f0.x, vj*f0.y, vj*f1.x, vj*f1.y));
    }
}

// ---------------------------------------------------------------------------
// GEMM2 (TF32 MMA): Z1 = relu(S1 + b1) @ W2   [n,64] @ [64,32], fp16 out.
// ---------------------------------------------------------------------------
#define Z_STRIDE 68
#define V_STRIDE 40

__global__ __launch_bounds__(256) void gemm2_mma_kernel(
    const float* __restrict__ b1, const float* __restrict__ W2, int n)
{
    __shared__ float    zs[128 * Z_STRIDE];
    __shared__ unsigned ws[64 * V_STRIDE];
    __shared__ float    b1s[64];

    int tid  = threadIdx.x;
    int warp = tid >> 5;
    int lane = tid & 31;
    int row_base = blockIdx.x * 128;
    int wm   = warp * 16;
    int qrow = lane >> 2;
    int qcol = lane & 3;

    unsigned zs_base;
    asm("{ .reg .u64 t; cvta.to.shared.u64 t, %1; cvt.u32.u64 %0, t; }"
        : "=r"(zs_base) : "l"(zs));

    #pragma unroll
    for (int l = 0; l < 8; l++) {
        int flat = tid + l * 256;
        int r  = flat >> 4;
        int c4 = flat & 15;
        int grow = row_base + r; if (grow >= n) grow = n - 1;
        cp_async16(zs_base + (unsigned)(r * Z_STRIDE + c4 * 4) * 4,
                   g_S1 + (size_t)grow * D_HID + c4 * 4);
    }
    asm volatile("cp.async.commit_group;");

    #pragma unroll
    for (int l = 0; l < 2; l++) {
        int flat = tid + l * 256;
        int k  = flat >> 3;
        int cc = (flat & 7) * 4;
        float4 w = __ldg((const float4*)(W2 + (size_t)k * 32 + cc));
        ws[k * V_STRIDE + cc + 0] = f2tf32(w.x);
        ws[k * V_STRIDE + cc + 1] = f2tf32(w.y);
        ws[k * V_STRIDE + cc + 2] = f2tf32(w.z);
        ws[k * V_STRIDE + cc + 3] = f2tf32(w.w);
    }
    if (tid < 64) b1s[tid] = __ldg(b1 + tid);

    asm volatile("cp.async.wait_group 0;");
    __syncthreads();

    float c[4][4];
    #pragma unroll
    for (int nt = 0; nt < 4; nt++)
        #pragma unroll
        for (int i = 0; i < 4; i++) c[nt][i] = 0.f;

    int ar = wm + qrow;
    #pragma unroll
    for (int k8 = 0; k8 < 8; k8++) {
        int k0 = k8 * 8 + qcol;
        float bz0 = b1s[k0];
        float bz1 = b1s[k0 + 4];
        unsigned a0 = f2tf32(fmaxf(zs[(ar    ) * Z_STRIDE + k0    ] + bz0, 0.f));
        unsigned a1 = f2tf32(fmaxf(zs[(ar + 8) * Z_STRIDE + k0    ] + bz0, 0.f));
        unsigned a2 = f2tf32(fmaxf(zs[(ar    ) * Z_STRIDE + k0 + 4] + bz1, 0.f));
        unsigned a3 = f2tf32(fmaxf(zs[(ar + 8) * Z_STRIDE + k0 + 4] + bz1, 0.f));
        #pragma unroll
        for (int nt = 0; nt < 4; nt++) {
            unsigned b0 = ws[(k0    ) * V_STRIDE + nt * 8 + qrow];
            unsigned b1v= ws[(k0 + 4) * V_STRIDE + nt * 8 + qrow];
            mma_tf32(c[nt][0], c[nt][1], c[nt][2], c[nt][3],
                     a0, a1, a2, a3, b0, b1v);
        }
    }

    int r0 = row_base + wm + qrow;
    int cb = qcol * 2;
    #pragma unroll
    for (int nt = 0; nt < 4; nt++) {
        if (r0 < n)
            *(__half2*)(g_Z1h + (size_t)r0 * D_EMB + nt*8 + cb) =
                __floats2half2_rn(c[nt][0], c[nt][1]);
        if (r0 + 8 < n)
            *(__half2*)(g_Z1h + (size_t)(r0 + 8) * D_EMB + nt*8 + cb) =
                __floats2half2_rn(c[nt][2], c[nt][3]);
    }
}

// ---------------------------------------------------------------------------
// SpMM d=32: warp owns 32 edges; coalesced streaming index loads + shfl.
// ---------------------------------------------------------------------------
__global__ __launch_bounds__(256) void spmm32_kernel(
    const int* __restrict__ src, const int* __restrict__ dst,
    const float* __restrict__ val, int nnz)
{
    int lane = threadIdx.x & 31;
    long long wid = (long long)((blockIdx.x * blockDim.x + threadIdx.x) >> 5);
    long long wbase = wid * 32;
    if (wbase >= nnz) return;

    long long e = wbase + lane;
    bool ok = (e < nnz);
    long long ec = ok ? e : (nnz - 1);
    int   s = __ldcs(src + ec);
    int   d = __ldcs(dst + ec);
    float v = ok ? __ldcs(val + ec) : 0.f;

    int g = lane >> 3;          // group 0..3
    int c = lane & 7;

    #pragma unroll
    for (int j = 0; j < 8; j++) {
        int sl = g * 8 + j;
        int   sj = __shfl_sync(0xFFFFFFFFu, s, sl);
        int   dj = __shfl_sync(0xFFFFFFFFu, d, sl);
        float vj = __shfl_sync(0xFFFFFFFFu, v, sl);
        uint2 raw = __ldg((const uint2*)(g_Z1h + (size_t)sj * D_EMB) + c);
        float2 f0 = __half22float2(*(__half2*)&raw.x);
        float2 f1 = __half22float2(*(__half2*)&raw.y);
        red_add_v4(g_S2 + (size_t)dj * D_EMB + c * 4,
                   make_float4(vj*f0.x, vj*f0.y, vj*f1.x, vj*f1.y));
    }
}

// ---------------------------------------------------------------------------
// S2 fp32 -> fp16 with fused +b2.
// ---------------------------------------------------------------------------
__global__ __launch_bounds__(256) void s2half_kernel(
    const float* __restrict__ b2, int n4)
{
    int i = blockIdx.x * blockDim.x + threadIdx.x;
    if (i >= n4) return;
    float4 bb = __ldg((const float4*)b2 + (i & 7));
    float4 v = ((const float4*)g_S2)[i];
    ((__half2*)g_S2h)[i*2    ] = __floats2half2_rn(v.x + bb.x, v.y + bb.y);
    ((__half2*)g_S2h)[i*2 + 1] = __floats2half2_rn(v.z + bb.z, v.w + bb.w);
}

// ---------------------------------------------------------------------------
// Decoder: warp owns 32 edges; coalesced index loads + shfl distribution.
// ---------------------------------------------------------------------------
__global__ __launch_bounds__(256) void decoder_kernel(
    const int* __restrict__ edge_index, float* __restrict__ out, int ne)
{
    int lane = threadIdx.x & 31;
    long long wid = (long long)((blockIdx.x * blockDim.x + threadIdx.x) >> 5);
    long long wbase = wid * 32;
    if (wbase >= ne) return;

    long long e = wbase + lane;
    bool ok = (e < ne);
    long long ec = ok ? e : (ne - 1);
    int s = __ldcs(edge_index + ec);
    int d = __ldcs(edge_index + ne + ec);

    int g = lane >> 3;
    int c = lane & 7;

    float p[8];
    #pragma unroll
    for (int j = 0; j < 8; j++) {
        int sl = g * 8 + j;
        int sj = __shfl_sync(0xFFFFFFFFu, s, sl);
        int dj = __shfl_sync(0xFFFFFFFFu, d, sl);
        uint2 ra = __ldg((const uint2*)(g_S2h + (size_t)sj * D_EMB) + c);
        uint2 rb = __ldg((const uint2*)(g_S2h + (size_t)dj * D_EMB) + c);
        float2 al = __half22float2(*(__half2*)&ra.x);
        float2 ah = __half22float2(*(__half2*)&ra.y);
        float2 bl = __half22float2(*(__half2*)&rb.x);
        float2 bh = __half22float2(*(__half2*)&rb.y);
        p[j] = al.x*bl.x + al.y*bl.y + ah.x*bh.x + ah.y*bh.y;
    }

    #pragma unroll
    for (int m = 1; m < 8; m <<= 1) {
        #pragma unroll
        for (int j = 0; j < 8; j++)
            p[j] += __shfl_xor_sync(0xFFFFFFFFu, p[j], m);
    }

    long long eo = wbase + g * 8 + c;
    if (eo < ne) out[eo] = p[c];
}

// ---------------------------------------------------------------------------
extern "C" void kernel_launch(void* const* d_in, const int* in_sizes, int n_in,
                              void* d_out, int out_size)
{
    const float* x         = (const float*)d_in[0];
    const int*   adj_src   = (const int*)  d_in[1];
    const int*   adj_dst   = (const int*)  d_in[2];
    const float* adj_val   = (const float*)d_in[3];
    const int*   edge_idx  = (const int*)  d_in[4];
    const float* W1        = (const float*)d_in[5];
    const float* b1        = (const float*)d_in[6];
    const float* W2        = (const float*)d_in[7];
    const float* b2        = (const float*)d_in[8];
    float*       out       = (float*)d_out;

    int n   = in_sizes[0] / D_IN;
    int nnz = in_sizes[3];
    int ne  = in_sizes[4] / 2;
    (void)n_in; (void)out_size;

    // GEMM1 (TF32, fragment-order W, cp.async double buffer, fused zeroing)
    cudaFuncSetAttribute(gemm1_tf32_v7,
                         cudaFuncAttributeMaxDynamicSharedMemorySize, GEMM1_SMEM);
    gemm1_tf32_v7<<<(n + 127) / 128, 256, GEMM1_SMEM>>>(x, W1, n);

    // SpMM1 (d=64): 1 warp per 32 edges
    {
        long long warps = ((long long)nnz + 31) / 32;
        long long total = warps * 32;
        int blocks = (int)((total + 255) / 256);
        spmm64_kernel<<<blocks, 256>>>(adj_src, adj_dst, adj_val, nnz);
    }
    // GEMM2 (TF32 MMA, fused relu + b1, fp16 Z1)
    gemm2_mma_kernel<<<(n + 127) / 128, 256>>>(b1, W2, n);
    // SpMM2 (d=32): 1 warp per 32 edges
    {
        long long warps = ((long long)nnz + 31) / 32;
        long long total = warps * 32;
        int blocks = (int)((total + 255) / 256);
        spmm32_kernel<<<blocks, 256>>>(adj_src, adj_dst, adj_val, nnz);
    }
    // S2 -> fp16 with +b2 folded
    {
        int n4 = n * 8;
        s2half_kernel<<<(n4 + 255) / 256, 256>>>(b2, n4);
    }
    // Decoder: 1 warp per 32 edges
    {
        long long warps = ((long long)ne + 31) / 32;
        long long total = warps * 32;
        int blocks = (int)((total + 255) / 256);
        decoder_kernel<<<blocks, 256>>>(edge_idx, out, ne);
    }
}